// round 17
// baseline (speedup 1.0000x reference)
#include <cuda_runtime.h>
#include <math.h>
#include <cstdint>

#define MAX_S 4096
__device__ float4 g_coeffs[2 * MAX_S];

#define BLOCK 128
#define OUT_TILE_BYTES (BLOCK * 32)   // 2 float4 per thread = 4096 B per block

__global__ void spline_coeff_kernel(const float2* __restrict__ ctrl,
                                    const float2* __restrict__ joint,
                                    int S) {
    int s = blockIdx.x * blockDim.x + threadIdx.x;
    if (s >= S) return;
    float2 p0 = joint[s];
    float2 p3 = joint[s + 1];
    float2 p1 = ctrl[2 * s];
    float2 p2 = ctrl[2 * s + 1];

    float c1x = 3.0f * (p1.x - p0.x);
    float c1y = 3.0f * (p1.y - p0.y);
    float c2x = 3.0f * p0.x - 6.0f * p1.x + 3.0f * p2.x;
    float c2y = 3.0f * p0.y - 6.0f * p1.y + 3.0f * p2.y;
    float c3x = -p0.x + 3.0f * p1.x - 3.0f * p2.x + p3.x;
    float c3y = -p0.y + 3.0f * p1.y - 3.0f * p2.y + p3.y;

    g_coeffs[2 * s + 0] = make_float4(p0.x, p0.y, c1x, c1y);
    g_coeffs[2 * s + 1] = make_float4(c2x, c2y, c3x, c3y);
}

__device__ __forceinline__ void eval_one(const float4& a, const float4& b,
                                         float l, float& x, float& y) {
    float l2 = l * l;
    float l3 = l2 * l;
    x = fmaf(b.z, l3, fmaf(b.x, l2, fmaf(a.z, l, a.x)));
    y = fmaf(b.w, l3, fmaf(b.y, l2, fmaf(a.w, l, a.y)));
}

// Post-sync part: everything that touches g_coeffs.
__device__ __forceinline__ void eval4_body(const float u[4], int lo, int hi,
                                           int S, float* rx, float* ry) {
    if (lo == hi && lo < S) {
        float4 a = __ldg(&g_coeffs[2 * lo + 0]);
        float4 b = __ldg(&g_coeffs[2 * lo + 1]);
        float sgf = (float)lo;
#pragma unroll
        for (int j = 0; j < 4; j++)
            eval_one(a, b, u[j] - sgf, rx[j], ry[j]);
    } else {
#pragma unroll
        for (int j = 0; j < 4; j++) {
            int sg = (int)u[j];
            float l = u[j] - (float)sg;
            if (sg >= S) { sg = S - 1; l = 1.0f; }
            float4 a = __ldg(&g_coeffs[2 * sg + 0]);
            float4 b = __ldg(&g_coeffs[2 * sg + 1]);
            eval_one(a, b, l, rx[j], ry[j]);
        }
    }
}

// Unguarded: grid * BLOCK == n4 exactly. PDL: prologue (t-load, clamp, shfl)
// runs concurrently with the coeff kernel; grid-dependency sync happens just
// before the first g_coeffs access.
__global__ void __launch_bounds__(BLOCK)
spline_eval_bulkout(const float4* __restrict__ t4, float4* __restrict__ out4,
                    float Sf, int S) {
    __shared__ alignas(128) float4 s_out[2 * BLOCK];

    const int tid = threadIdx.x;
    const int i = blockIdx.x * BLOCK + tid;

    // ---- pre-dependency prologue (independent of g_coeffs) ----
    float4 tv = t4[i];
    float u[4];
    u[0] = Sf * fminf(tv.x, 1.0f);
    u[1] = Sf * fminf(tv.y, 1.0f);
    u[2] = Sf * fminf(tv.z, 1.0f);
    u[3] = Sf * fminf(tv.w, 1.0f);
    int lo = __shfl_sync(0xFFFFFFFFu, (int)u[0], 0);
    int hi = __shfl_sync(0xFFFFFFFFu, (int)u[3], 31);

    // ---- wait for coeff kernel before touching g_coeffs ----
    cudaGridDependencySynchronize();

    float rx[4], ry[4];
    eval4_body(u, lo, hi, S, rx, ry);

    s_out[2 * tid + 0] = make_float4(rx[0], ry[0], rx[1], ry[1]);
    s_out[2 * tid + 1] = make_float4(rx[2], ry[2], rx[3], ry[3]);

    __syncthreads();

    if (tid == 0) {
        uint32_t src = (uint32_t)__cvta_generic_to_shared(&s_out[0]);
        float4* dst = out4 + 2 * (size_t)blockIdx.x * BLOCK;
        asm volatile("fence.proxy.async.shared::cta;" ::: "memory");
        asm volatile("cp.async.bulk.global.shared::cta.bulk_group [%0], [%1], %2;"
                     :: "l"(dst), "r"(src), "n"(OUT_TILE_BYTES) : "memory");
        asm volatile("cp.async.bulk.commit_group;" ::: "memory");
        asm volatile("cp.async.bulk.wait_group.read 0;" ::: "memory");
    }
}

// Guarded fallback for non-divisible n4 (plain stores).
__global__ void __launch_bounds__(BLOCK)
spline_eval_guard(const float4* __restrict__ t4, float4* __restrict__ out4,
                  int n4, float Sf, int S) {
    int i = blockIdx.x * BLOCK + threadIdx.x;
    bool valid = i < n4;
    int ii = valid ? i : (n4 - 1);
    float4 tv = t4[ii];
    float u[4];
    u[0] = Sf * fminf(tv.x, 1.0f);
    u[1] = Sf * fminf(tv.y, 1.0f);
    u[2] = Sf * fminf(tv.z, 1.0f);
    u[3] = Sf * fminf(tv.w, 1.0f);
    int lo = __shfl_sync(0xFFFFFFFFu, (int)u[0], 0);
    int hi = __shfl_sync(0xFFFFFFFFu, (int)u[3], 31);
    cudaGridDependencySynchronize();
    float rx[4], ry[4];
    eval4_body(u, lo, hi, S, rx, ry);
    if (valid) {
        out4[2 * i + 0] = make_float4(rx[0], ry[0], rx[1], ry[1]);
        out4[2 * i + 1] = make_float4(rx[2], ry[2], rx[3], ry[3]);
    }
}

// Scalar tail for n % 4 != 0 (not hit for N = 8388608)
__global__ void spline_eval_tail(const float* __restrict__ t,
                                 float2* __restrict__ out,
                                 int start, int n, float Sf, int S) {
    int i = start + blockIdx.x * blockDim.x + threadIdx.x;
    if (i >= n) return;
    cudaGridDependencySynchronize();
    float u = Sf * fminf(t[i], 1.0f);
    int sg = (int)u;
    float l = u - (float)sg;
    if (sg >= S) { sg = S - 1; l = 1.0f; }
    float4 a = __ldg(&g_coeffs[2 * sg + 0]);
    float4 b = __ldg(&g_coeffs[2 * sg + 1]);
    float x, y;
    eval_one(a, b, l, x, y);
    out[i] = make_float2(x, y);
}

extern "C" void kernel_launch(void* const* d_in, const int* in_sizes, int n_in,
                              void* d_out, int out_size) {
    const float* t = (const float*)d_in[0];
    const float2* ctrl = (const float2*)d_in[1];
    const float2* joint = (const float2*)d_in[2];

    int n = in_sizes[0];
    int S = in_sizes[2] / 2 - 1;

    {
        int threads = 128;
        int blocks = (S + threads - 1) / threads;
        spline_coeff_kernel<<<blocks, threads>>>(ctrl, joint, S);
    }

    // PDL launch attribute: allow eval to start during the coeff kernel;
    // the in-kernel cudaGridDependencySynchronize gates g_coeffs access.
    cudaLaunchAttribute attrs[1];
    attrs[0].id = cudaLaunchAttributeProgrammaticStreamSerialization;
    attrs[0].val.programmaticStreamSerializationAllowed = 1;

    int n4 = n / 4;
    if (n4 > 0) {
        cudaLaunchConfig_t cfg = {};
        cfg.blockDim = {BLOCK, 1, 1};
        cfg.attrs = attrs;
        cfg.numAttrs = 1;
        if (n4 % BLOCK == 0) {
            cfg.gridDim = {(unsigned)(n4 / BLOCK), 1, 1};
            cudaLaunchKernelEx(&cfg, spline_eval_bulkout,
                               (const float4*)t, (float4*)d_out, (float)S, S);
        } else {
            cfg.gridDim = {(unsigned)((n4 + BLOCK - 1) / BLOCK), 1, 1};
            cudaLaunchKernelEx(&cfg, spline_eval_guard,
                               (const float4*)t, (float4*)d_out, n4, (float)S, S);
        }
    }
    int rem = n - n4 * 4;
    if (rem > 0) {
        cudaLaunchConfig_t cfg = {};
        cfg.blockDim = {128, 1, 1};
        cfg.gridDim = {1, 1, 1};
        cfg.attrs = attrs;
        cfg.numAttrs = 1;
        cudaLaunchKernelEx(&cfg, spline_eval_tail,
                           t, (float2*)d_out, n4 * 4, n, (float)S, S);
    }
}